// round 3
// baseline (speedup 1.0000x reference)
#include <cuda_runtime.h>
#include <math.h>

// Inputs (metadata order): y[16M] f32, mu[16M] f32, std[16M] f32, idx[200*100] i32
// Output: 1 x f32 (KL scalar)

#define NUM_SAMPLES 200
#define KDOF 100

// Scratch (no device allocation allowed). Reset by the last block each launch
// so graph replays see a clean state (deterministic work every call).
__device__ double       g_sum_q  = 0.0;
__device__ double       g_sum_q2 = 0.0;
__device__ unsigned int g_count  = 0;

// 200 blocks x 128 threads. Each block computes q[s] for its sample, folds it
// into fp64 running sums via atomics; the LAST block computes the KL scalar.
__global__ void __launch_bounds__(128) fused_chi2_kl_kernel(
    const float* __restrict__ y,
    const float* __restrict__ mu,
    const float* __restrict__ sd,
    const int*   __restrict__ idx,
    float*       __restrict__ out)
{
    const int s = blockIdx.x;
    const int t = threadIdx.x;

    // ---- Phase 1: per-sample chi-square statistic ----
    float v = 0.0f;
    if (t < KDOF) {
        const int i = idx[s * KDOF + t];
        // three independent loads -> MLP=3, latency pipelined
        const float d = (y[i] - mu[i]) / sd[i];
        v = d * d;
    }

    #pragma unroll
    for (int o = 16; o > 0; o >>= 1)
        v += __shfl_down_sync(0xFFFFFFFFu, v, o);

    __shared__ float sm[4];
    if ((t & 31) == 0) sm[t >> 5] = v;
    __syncthreads();

    if (t != 0) return;   // only thread 0 of each block continues

    const float q = sm[0] + sm[1] + sm[2] + sm[3];

    // Fold into fp64 accumulators (exact enough: |q| ~ 1e2, n = 200).
    atomicAdd(&g_sum_q,  (double)q);
    atomicAdd(&g_sum_q2, (double)q * (double)q);
    __threadfence();                        // publish sums before the ticket

    const unsigned int prev = atomicAdd(&g_count, 1u);
    if (prev != NUM_SAMPLES - 1u) return;

    // ---- Phase 2 (single thread of the last block): KL ----
    __threadfence();                        // acquire: see all atomic sums

    const double sq  = g_sum_q;
    const double sq2 = g_sum_q2;

    const double n    = (double)NUM_SAMPLES;
    const double mean = sq / n;
    const double var  = (sq2 - sq * sq / n) / (n - 1.0);

    const double k     = (double)KDOF;
    const double two_k = 2.0 * k;
    const double dm    = mean - k;
    const double kl = 0.5 * log(two_k / var)
                    + (var + dm * dm) / (2.0 * two_k)
                    - 0.5;

    out[0] = (float)kl;

    // Reset scratch for the next graph replay.
    g_sum_q  = 0.0;
    g_sum_q2 = 0.0;
    g_count  = 0;
}

extern "C" void kernel_launch(void* const* d_in, const int* in_sizes, int n_in,
                              void* d_out, int out_size)
{
    const float* y   = (const float*)d_in[0];
    const float* mu  = (const float*)d_in[1];
    const float* sd  = (const float*)d_in[2];
    const int*   idx = (const int*)d_in[3];
    float* out = (float*)d_out;

    fused_chi2_kl_kernel<<<NUM_SAMPLES, 128>>>(y, mu, sd, idx, out);
}